// round 12
// baseline (speedup 1.0000x reference)
#include <cuda_runtime.h>
#include <cstdint>

// ROI adaptive average pooling: one WARP per (b, s, channel-group-of-4).
// R12 = R11 with unroll 8->6 (narrow) / 4->3 (wide) to cut the register
// buffers, and __launch_bounds__(256, 5) -> 5 blocks/SM (occ 45% -> ~56%).
//
// One LDG.128 per lane per row covers 4 channels x 32 window cols:
//   quarter = lane>>3 -> channel c0+quarter
//   k       = lane&7  -> float4 slot, window cols 4k..4k+3
// Window starts at x1 & ~3 (off = x1&3 junk cols skipped in phase 2).
// Band straddle via double accumulator: a += v always; n += v when
// rr >= syn (warp-uniform); at transition flush a, a = n, n = 0.
//
// x:    [B=8, C=64, H=256, W=256] fp32
// rois: [B=8, S=128, 5] int32 (idx, x1, y1, x2, y2); sides in [8,40]
// out:  [B, S*C, 7, 7] fp32; torch adaptive-pool integer bin bounds.

namespace {
constexpr int B  = 8;
constexpr int C  = 64;
constexpr int H  = 256;
constexpr int W  = 256;
constexpr int S  = 128;
constexpr int OH = 7;
constexpr int OW = 7;
constexpr int CH = H * W;
constexpr int W4 = W / 4;          // row stride in float4
constexpr int PITCH = 44;          // smem strip cols (aligned window width)

constexpr int NCH = 4;
constexpr int WPB = 8;
constexpr int THREADS = WPB * 32;
constexpr int NTASK = B * S * (C / NCH);  // 16384
constexpr int NBLOCK = NTASK / WPB;       // 2048

constexpr int UN = 6;              // narrow-path unroll
constexpr int UW = 3;              // wide-path unroll
}

__device__ __forceinline__ void fadd4(float4& a, const float4& v) {
    a.x += v.x; a.y += v.y; a.z += v.z; a.w += v.w;
}

__global__ void __launch_bounds__(THREADS, 5) roi_pool_f5_kernel(
    const float* __restrict__ x,
    const int*   __restrict__ rois,
    float*       __restrict__ out)
{
    __shared__ float cs_all[WPB][NCH][OH][PITCH];   // 8*4*7*44*4 = 39424 B

    const int lane = threadIdx.x & 31;
    const int warp = threadIdx.x >> 5;

    const int task = blockIdx.x * WPB + warp;
    const int cg   = task & (C / NCH - 1);
    const int bs   = task >> 4;              // b*S + s
    const int b    = bs >> 7;
    const int c0   = cg * NCH;

    const int* r = rois + bs * 5;
    const int x1 = r[1];
    const int y1 = r[2];
    const int w  = r[3] - x1;                // [8,40]
    const int h  = r[4] - y1;                // [8,40]

    const int off = x1 & 3;
    const int x1a = x1 - off;

    const int quarter = lane >> 3;           // channel within group
    const int k       = lane & 7;            // float4 slot: cols 4k..4k+3

    const float4* rowp = reinterpret_cast<const float4*>(
        x + (size_t)(b * C + c0 + quarter) * CH + (size_t)y1 * W + x1a);

    float (*cs)[OH][PITCH] = cs_all[warp];
    const float4 z4 = make_float4(0.f, 0.f, 0.f, 0.f);

    if (off + w <= 32) {
        // ---------------- narrow: 1 LDG.128/row, unroll UN ----------------
        float4 a = z4, n = z4;
        int cur = 0;
        int eyc = (h + 6) / 7;                       // ceil((cur+1)h/7)
        int syn = h / 7;                             // floor((cur+1)h/7)
        const float4* p = rowp + k;
        int r0 = 0;

        for (; r0 + UN <= h; r0 += UN, p += UN * W4) {
            float4 v[UN];
            #pragma unroll
            for (int i = 0; i < UN; ++i)
                v[i] = __ldg(p + i * W4);
            #pragma unroll
            for (int i = 0; i < UN; ++i) {
                const int rr = r0 + i;
                if (rr == eyc) {                     // transition (warp-uniform, rare)
                    *reinterpret_cast<float4*>(&cs[quarter][cur][4 * k]) = a;
                    a = n; n = z4;
                    ++cur;
                    eyc = ((cur + 1) * h + 6) / 7;
                    syn = ((cur + 1) * h) / 7;
                }
                fadd4(a, v[i]);
                if (rr >= syn)                        // straddle row (warp-uniform)
                    fadd4(n, v[i]);
            }
        }
        for (; r0 < h; ++r0, p += W4) {              // tail rows
            float4 v = __ldg(p);
            if (r0 == eyc) {
                *reinterpret_cast<float4*>(&cs[quarter][cur][4 * k]) = a;
                a = n; n = z4;
                ++cur;
                eyc = ((cur + 1) * h + 6) / 7;
                syn = ((cur + 1) * h) / 7;
            }
            fadd4(a, v);
            if (r0 >= syn)
                fadd4(n, v);
        }
        *reinterpret_cast<float4*>(&cs[quarter][6][4 * k]) = a;   // cur==6
    } else {
        // ------- wide (off+w in 33..43): main + 3 ext slots, unroll UW -------
        const bool ext = (k < 3);
        const float4* p  = rowp + k;
        const float4* pe = rowp + 8 + (ext ? k : 0); // cols 32..43 (always in-row)
        float4 a = z4, n = z4, ae = z4, ne = z4;
        int cur = 0;
        int eyc = (h + 6) / 7;
        int syn = h / 7;
        int r0 = 0;

        for (; r0 + UW <= h; r0 += UW, p += UW * W4, pe += UW * W4) {
            float4 v[UW], ve[UW];
            #pragma unroll
            for (int i = 0; i < UW; ++i) {
                v[i]  = __ldg(p + i * W4);
                ve[i] = ext ? __ldg(pe + i * W4) : z4;
            }
            #pragma unroll
            for (int i = 0; i < UW; ++i) {
                const int rr = r0 + i;
                if (rr == eyc) {
                    *reinterpret_cast<float4*>(&cs[quarter][cur][4 * k]) = a;
                    if (ext)
                        *reinterpret_cast<float4*>(&cs[quarter][cur][32 + 4 * k]) = ae;
                    a = n; ae = ne; n = z4; ne = z4;
                    ++cur;
                    eyc = ((cur + 1) * h + 6) / 7;
                    syn = ((cur + 1) * h) / 7;
                }
                fadd4(a, v[i]);
                fadd4(ae, ve[i]);
                if (rr >= syn) {
                    fadd4(n, v[i]);
                    fadd4(ne, ve[i]);
                }
            }
        }
        for (; r0 < h; ++r0, p += W4, pe += W4) {
            float4 v  = __ldg(p);
            float4 ve = ext ? __ldg(pe) : z4;
            if (r0 == eyc) {
                *reinterpret_cast<float4*>(&cs[quarter][cur][4 * k]) = a;
                if (ext)
                    *reinterpret_cast<float4*>(&cs[quarter][cur][32 + 4 * k]) = ae;
                a = n; ae = ne; n = z4; ne = z4;
                ++cur;
                eyc = ((cur + 1) * h + 6) / 7;
                syn = ((cur + 1) * h) / 7;
            }
            fadd4(a, v);
            fadd4(ae, ve);
            if (r0 >= syn) {
                fadd4(n, v);
                fadd4(ne, ve);
            }
        }
        *reinterpret_cast<float4*>(&cs[quarter][6][4 * k]) = a;
        if (ext)
            *reinterpret_cast<float4*>(&cs[quarter][6][32 + 4 * k]) = ae;
    }
    __syncwarp();

    // ---- phase 2: bins from column sums (crop col j at smem index off+j) ----
    float* obase = out + (size_t)(bs * C + c0) * (OH * OW);
    for (int t = lane; t < OH * OW; t += 32) {
        const int oy = t / OW;
        const int ox = t - oy * OW;

        const int sx = (ox * w) / OW;
        const int ex = ((ox + 1) * w + (OW - 1)) / OW;
        const int sy = (oy * h) / OH;
        const int ey = ((oy + 1) * h + (OH - 1)) / OH;

        float q0 = 0.f, q1 = 0.f, q2 = 0.f, q3 = 0.f;
        #pragma unroll 4
        for (int xx = off + sx; xx < off + ex; ++xx) {
            q0 += cs[0][oy][xx];
            q1 += cs[1][oy][xx];
            q2 += cs[2][oy][xx];
            q3 += cs[3][oy][xx];
        }

        const float inv = 1.0f / (float)((ey - sy) * (ex - sx));
        obase[t]               = q0 * inv;
        obase[t +     OH * OW] = q1 * inv;
        obase[t + 2 * OH * OW] = q2 * inv;
        obase[t + 3 * OH * OW] = q3 * inv;
    }
}

extern "C" void kernel_launch(void* const* d_in, const int* in_sizes, int n_in,
                              void* d_out, int out_size)
{
    const float* x    = (const float*)d_in[0];
    const int*   rois = (const int*)d_in[1];
    float*       out  = (float*)d_out;

    roi_pool_f5_kernel<<<NBLOCK, THREADS>>>(x, rois, out);
}

// round 13
// speedup vs baseline: 1.6846x; 1.6846x over previous
#include <cuda_runtime.h>
#include <cstdint>

// ROI adaptive average pooling: one WARP per (b, s, channel-group-of-4).
// R13 = R11 + software pipelining: double-buffered 4-row groups (narrow) /
// 2-row groups (wide); prefetch group g+1 before accumulating group g so
// LDG.128s are continuously in flight (R11 load duty cycle ~20%).
//
// One LDG.128 per lane per row covers 4 channels x 32 window cols:
//   quarter = lane>>3 -> channel c0+quarter
//   k       = lane&7  -> float4 slot, window cols 4k..4k+3
// Window starts at x1 & ~3 (off = x1&3 junk cols skipped in phase 2).
// Straddle via double accumulator: a += v always; n += v when rr >= syn
// (warp-uniform); at transition flush a, a = n, n = 0.
// Prefetch rows >= h redirect to row 0 (valid memory, never accumulated).
//
// x:    [B=8, C=64, H=256, W=256] fp32
// rois: [B=8, S=128, 5] int32 (idx, x1, y1, x2, y2); sides in [8,40]
// out:  [B, S*C, 7, 7] fp32; torch adaptive-pool integer bin bounds.

namespace {
constexpr int B  = 8;
constexpr int C  = 64;
constexpr int H  = 256;
constexpr int W  = 256;
constexpr int S  = 128;
constexpr int OH = 7;
constexpr int OW = 7;
constexpr int CH = H * W;
constexpr int W4 = W / 4;          // row stride in float4
constexpr int PITCH = 44;          // smem strip cols (aligned window width)

constexpr int NCH = 4;
constexpr int WPB = 8;
constexpr int THREADS = WPB * 32;
constexpr int NTASK = B * S * (C / NCH);  // 16384
constexpr int NBLOCK = NTASK / WPB;       // 2048
}

__device__ __forceinline__ void fadd4(float4& a, const float4& v) {
    a.x += v.x; a.y += v.y; a.z += v.z; a.w += v.w;
}

__global__ void __launch_bounds__(THREADS, 4) roi_pool_pipe_kernel(
    const float* __restrict__ x,
    const int*   __restrict__ rois,
    float*       __restrict__ out)
{
    __shared__ float cs_all[WPB][NCH][OH][PITCH];   // 39424 B

    const int lane = threadIdx.x & 31;
    const int warp = threadIdx.x >> 5;

    const int task = blockIdx.x * WPB + warp;
    const int cg   = task & (C / NCH - 1);
    const int bs   = task >> 4;              // b*S + s
    const int b    = bs >> 7;
    const int c0   = cg * NCH;

    const int* r = rois + bs * 5;
    const int x1 = r[1];
    const int y1 = r[2];
    const int w  = r[3] - x1;                // [8,40]
    const int h  = r[4] - y1;                // [8,40]

    const int off = x1 & 3;
    const int x1a = x1 - off;

    const int quarter = lane >> 3;           // channel within group
    const int k       = lane & 7;            // float4 slot: cols 4k..4k+3

    const float4* rowp = reinterpret_cast<const float4*>(
        x + (size_t)(b * C + c0 + quarter) * CH + (size_t)y1 * W + x1a);

    float (*cs)[OH][PITCH] = cs_all[warp];
    const float4 z4 = make_float4(0.f, 0.f, 0.f, 0.f);

    if (off + w <= 32) {
        // ------------- narrow: pipelined 4-row groups, double buffer -------------
        const float4* ps = rowp + k;             // row 0 (always-valid fallback)
        float4 a = z4, n = z4;
        int cur = 0;
        int eyc = (h + 6) / 7;                   // ceil((cur+1)h/7)
        int syn = h / 7;                         // floor((cur+1)h/7)

        float4 va[4], vb[4];
        #pragma unroll
        for (int i = 0; i < 4; ++i)              // preload rows 0..3 (h >= 8)
            va[i] = __ldg(ps + i * W4);
        const float4* p = ps + 4 * W4;           // prefetch base (rows r0+4..)
        int r0 = 0;

        #define NARROW_STEP(VPRE, VPROC)                                          \
        {                                                                         \
            _Pragma("unroll")                                                     \
            for (int i = 0; i < 4; ++i) {                                         \
                const float4* q = (r0 + 4 + i < h) ? (p + i * W4) : ps;           \
                VPRE[i] = __ldg(q);                                               \
            }                                                                     \
            p += 4 * W4;                                                          \
            _Pragma("unroll")                                                     \
            for (int i = 0; i < 4; ++i) {                                         \
                const int rr = r0 + i;                                            \
                if (rr < h) {                                                     \
                    if (rr == eyc) {                                              \
                        *reinterpret_cast<float4*>(&cs[quarter][cur][4 * k]) = a; \
                        a = n; n = z4;                                            \
                        ++cur;                                                    \
                        eyc = ((cur + 1) * h + 6) / 7;                            \
                        syn = ((cur + 1) * h) / 7;                                \
                    }                                                             \
                    fadd4(a, VPROC[i]);                                           \
                    if (rr >= syn)                                                \
                        fadd4(n, VPROC[i]);                                       \
                }                                                                 \
            }                                                                     \
            r0 += 4;                                                              \
        }

        for (;;) {
            NARROW_STEP(vb, va)
            if (r0 >= h) break;
            NARROW_STEP(va, vb)
            if (r0 >= h) break;
        }
        #undef NARROW_STEP
        *reinterpret_cast<float4*>(&cs[quarter][6][4 * k]) = a;   // cur==6
    } else {
        // ------- wide (off+w in 33..43): pipelined 2-row groups, double buffer -------
        const bool ext = (k < 3);
        const float4* ps  = rowp + k;
        const float4* pse = rowp + 8 + (ext ? k : 0);  // cols 32..43, row 0
        float4 a = z4, n = z4, ae = z4, ne = z4;
        int cur = 0;
        int eyc = (h + 6) / 7;
        int syn = h / 7;

        float4 va[2], vea[2], vb[2], veb[2];
        #pragma unroll
        for (int i = 0; i < 2; ++i) {                  // preload rows 0..1
            va[i]  = __ldg(ps + i * W4);
            vea[i] = ext ? __ldg(pse + i * W4) : z4;
        }
        const float4* p  = ps + 2 * W4;
        const float4* pe = pse + 2 * W4;
        int r0 = 0;

        #define WIDE_STEP(VPRE, VEPRE, VPROC, VEPROC)                             \
        {                                                                         \
            _Pragma("unroll")                                                     \
            for (int i = 0; i < 2; ++i) {                                         \
                const bool ok = (r0 + 2 + i < h);                                 \
                const float4* q  = ok ? (p + i * W4)  : ps;                       \
                const float4* qe = ok ? (pe + i * W4) : pse;                      \
                VPRE[i]  = __ldg(q);                                              \
                VEPRE[i] = ext ? __ldg(qe) : z4;                                  \
            }                                                                     \
            p += 2 * W4; pe += 2 * W4;                                            \
            _Pragma("unroll")                                                     \
            for (int i = 0; i < 2; ++i) {                                         \
                const int rr = r0 + i;                                            \
                if (rr < h) {                                                     \
                    if (rr == eyc) {                                              \
                        *reinterpret_cast<float4*>(&cs[quarter][cur][4 * k]) = a; \
                        if (ext)                                                  \
                            *reinterpret_cast<float4*>(                           \
                                &cs[quarter][cur][32 + 4 * k]) = ae;              \
                        a = n; ae = ne; n = z4; ne = z4;                          \
                        ++cur;                                                    \
                        eyc = ((cur + 1) * h + 6) / 7;                            \
                        syn = ((cur + 1) * h) / 7;                                \
                    }                                                             \
                    fadd4(a, VPROC[i]);                                           \
                    fadd4(ae, VEPROC[i]);                                         \
                    if (rr >= syn) {                                              \
                        fadd4(n, VPROC[i]);                                       \
                        fadd4(ne, VEPROC[i]);                                     \
                    }                                                             \
                }                                                                 \
            }                                                                     \
            r0 += 2;                                                              \
        }

        for (;;) {
            WIDE_STEP(vb, veb, va, vea)
            if (r0 >= h) break;
            WIDE_STEP(va, vea, vb, veb)
            if (r0 >= h) break;
        }
        #undef WIDE_STEP
        *reinterpret_cast<float4*>(&cs[quarter][6][4 * k]) = a;
        if (ext)
            *reinterpret_cast<float4*>(&cs[quarter][6][32 + 4 * k]) = ae;
    }
    __syncwarp();

    // ---- phase 2: bins from column sums (crop col j at smem index off+j) ----
    float* obase = out + (size_t)(bs * C + c0) * (OH * OW);
    for (int t = lane; t < OH * OW; t += 32) {
        const int oy = t / OW;
        const int ox = t - oy * OW;

        const int sx = (ox * w) / OW;
        const int ex = ((ox + 1) * w + (OW - 1)) / OW;
        const int sy = (oy * h) / OH;
        const int ey = ((oy + 1) * h + (OH - 1)) / OH;

        float q0 = 0.f, q1 = 0.f, q2 = 0.f, q3 = 0.f;
        #pragma unroll 4
        for (int xx = off + sx; xx < off + ex; ++xx) {
            q0 += cs[0][oy][xx];
            q1 += cs[1][oy][xx];
            q2 += cs[2][oy][xx];
            q3 += cs[3][oy][xx];
        }

        const float inv = 1.0f / (float)((ey - sy) * (ex - sx));
        obase[t]               = q0 * inv;
        obase[t +     OH * OW] = q1 * inv;
        obase[t + 2 * OH * OW] = q2 * inv;
        obase[t + 3 * OH * OW] = q3 * inv;
    }
}

extern "C" void kernel_launch(void* const* d_in, const int* in_sizes, int n_in,
                              void* d_out, int out_size)
{
    const float* x    = (const float*)d_in[0];
    const int*   rois = (const int*)d_in[1];
    float*       out  = (float*)d_out;

    roi_pool_pipe_kernel<<<NBLOCK, THREADS>>>(x, rois, out);
}

// round 14
// speedup vs baseline: 1.7391x; 1.0324x over previous
#include <cuda_runtime.h>
#include <cstdint>

// ROI adaptive average pooling: one WARP per (b, s, channel-group-of-4).
// R14 = R11 load structure (LDG.128, unroll 8 narrow / 4 wide, 4 blocks/SM)
// with straddle-by-renaming: at a band transition the straddle row is always
// the previously processed row -> v[i-1] in-group / vlast across groups.
// Removes the per-row (ISETP + 4 predicated FADD) of the double-accumulator.
//
// One LDG.128 per lane per row covers 4 channels x 32 window cols:
//   quarter = lane>>3 -> channel c0+quarter
//   k       = lane&7  -> float4 slot, window cols 4k..4k+3
// Window starts at x1 & ~3 (off = x1&3 junk cols skipped in phase 2).
//
// x:    [B=8, C=64, H=256, W=256] fp32
// rois: [B=8, S=128, 5] int32 (idx, x1, y1, x2, y2); sides in [8,40]
// out:  [B, S*C, 7, 7] fp32; torch adaptive-pool integer bin bounds.

namespace {
constexpr int B  = 8;
constexpr int C  = 64;
constexpr int H  = 256;
constexpr int W  = 256;
constexpr int S  = 128;
constexpr int OH = 7;
constexpr int OW = 7;
constexpr int CH = H * W;
constexpr int W4 = W / 4;          // row stride in float4
constexpr int PITCH = 44;          // smem strip cols (aligned window width)

constexpr int NCH = 4;
constexpr int WPB = 8;
constexpr int THREADS = WPB * 32;
constexpr int NTASK = B * S * (C / NCH);  // 16384
constexpr int NBLOCK = NTASK / WPB;       // 2048
}

__device__ __forceinline__ void fadd4(float4& a, const float4& v) {
    a.x += v.x; a.y += v.y; a.z += v.z; a.w += v.w;
}

__global__ void __launch_bounds__(THREADS, 4) roi_pool_ren_kernel(
    const float* __restrict__ x,
    const int*   __restrict__ rois,
    float*       __restrict__ out)
{
    __shared__ float cs_all[WPB][NCH][OH][PITCH];   // 39424 B

    const int lane = threadIdx.x & 31;
    const int warp = threadIdx.x >> 5;

    const int task = blockIdx.x * WPB + warp;
    const int cg   = task & (C / NCH - 1);
    const int bs   = task >> 4;              // b*S + s
    const int b    = bs >> 7;
    const int c0   = cg * NCH;

    const int* r = rois + bs * 5;
    const int x1 = r[1];
    const int y1 = r[2];
    const int w  = r[3] - x1;                // [8,40]
    const int h  = r[4] - y1;                // [8,40]

    const int off = x1 & 3;
    const int x1a = x1 - off;

    const int quarter = lane >> 3;           // channel within group
    const int k       = lane & 7;            // float4 slot: cols 4k..4k+3

    const float4* rowp = reinterpret_cast<const float4*>(
        x + (size_t)(b * C + c0 + quarter) * CH + (size_t)y1 * W + x1a);

    float (*cs)[OH][PITCH] = cs_all[warp];
    const float4 z4 = make_float4(0.f, 0.f, 0.f, 0.f);

    if (off + w <= 32) {
        // ---------------- narrow: 1 LDG.128/row, unroll 8 ----------------
        float4 a = z4;
        float4 vlast = z4;                           // prev row (cross-group)
        int cur = 0;
        int eyc = (h + 6) / 7;                       // ceil((cur+1)h/7)
        int syn = h / 7;                             // floor((cur+1)h/7)
        const float4* p = rowp + k;
        int r0 = 0;

        for (; r0 + 8 <= h; r0 += 8, p += 8 * W4) {
            float4 v[8];
            #pragma unroll
            for (int i = 0; i < 8; ++i)
                v[i] = __ldg(p + i * W4);
            #pragma unroll
            for (int i = 0; i < 8; ++i) {
                const int rr = r0 + i;
                if (rr == eyc) {                     // transition (warp-uniform, rare)
                    *reinterpret_cast<float4*>(&cs[quarter][cur][4 * k]) = a;
                    if (eyc > syn)                   // straddle: prev row's value
                        a = (i == 0) ? vlast : v[i - 1];
                    else
                        a = z4;
                    ++cur;
                    eyc = ((cur + 1) * h + 6) / 7;
                    syn = ((cur + 1) * h) / 7;
                }
                fadd4(a, v[i]);
            }
            vlast = v[7];
        }
        for (; r0 < h; ++r0, p += W4) {              // tail rows
            float4 v = __ldg(p);
            if (r0 == eyc) {
                *reinterpret_cast<float4*>(&cs[quarter][cur][4 * k]) = a;
                a = (eyc > syn) ? vlast : z4;
                ++cur;
                eyc = ((cur + 1) * h + 6) / 7;
                syn = ((cur + 1) * h) / 7;
            }
            fadd4(a, v);
            vlast = v;
        }
        *reinterpret_cast<float4*>(&cs[quarter][6][4 * k]) = a;   // cur==6
    } else {
        // ------- wide (off+w in 33..43): main + 3 ext slots, unroll 4 -------
        const bool ext = (k < 3);
        const float4* p  = rowp + k;
        const float4* pe = rowp + 8 + (ext ? k : 0); // cols 32..43 (always in-row)
        float4 a = z4, ae = z4;
        float4 vlast = z4, velast = z4;
        int cur = 0;
        int eyc = (h + 6) / 7;
        int syn = h / 7;
        int r0 = 0;

        for (; r0 + 4 <= h; r0 += 4, p += 4 * W4, pe += 4 * W4) {
            float4 v[4], ve[4];
            #pragma unroll
            for (int i = 0; i < 4; ++i) {
                v[i]  = __ldg(p + i * W4);
                ve[i] = ext ? __ldg(pe + i * W4) : z4;
            }
            #pragma unroll
            for (int i = 0; i < 4; ++i) {
                const int rr = r0 + i;
                if (rr == eyc) {
                    *reinterpret_cast<float4*>(&cs[quarter][cur][4 * k]) = a;
                    if (ext)
                        *reinterpret_cast<float4*>(&cs[quarter][cur][32 + 4 * k]) = ae;
                    if (eyc > syn) {
                        a  = (i == 0) ? vlast  : v[i - 1];
                        ae = (i == 0) ? velast : ve[i - 1];
                    } else {
                        a = z4; ae = z4;
                    }
                    ++cur;
                    eyc = ((cur + 1) * h + 6) / 7;
                    syn = ((cur + 1) * h) / 7;
                }
                fadd4(a, v[i]);
                fadd4(ae, ve[i]);
            }
            vlast = v[3]; velast = ve[3];
        }
        for (; r0 < h; ++r0, p += W4, pe += W4) {
            float4 v  = __ldg(p);
            float4 ve = ext ? __ldg(pe) : z4;
            if (r0 == eyc) {
                *reinterpret_cast<float4*>(&cs[quarter][cur][4 * k]) = a;
                if (ext)
                    *reinterpret_cast<float4*>(&cs[quarter][cur][32 + 4 * k]) = ae;
                if (eyc > syn) {
                    a = vlast; ae = velast;
                } else {
                    a = z4; ae = z4;
                }
                ++cur;
                eyc = ((cur + 1) * h + 6) / 7;
                syn = ((cur + 1) * h) / 7;
            }
            fadd4(a, v);
            fadd4(ae, ve);
            vlast = v; velast = ve;
        }
        *reinterpret_cast<float4*>(&cs[quarter][6][4 * k]) = a;
        if (ext)
            *reinterpret_cast<float4*>(&cs[quarter][6][32 + 4 * k]) = ae;
    }
    __syncwarp();

    // ---- phase 2: bins from column sums (crop col j at smem index off+j) ----
    float* obase = out + (size_t)(bs * C + c0) * (OH * OW);
    for (int t = lane; t < OH * OW; t += 32) {
        const int oy = t / OW;
        const int ox = t - oy * OW;

        const int sx = (ox * w) / OW;
        const int ex = ((ox + 1) * w + (OW - 1)) / OW;
        const int sy = (oy * h) / OH;
        const int ey = ((oy + 1) * h + (OH - 1)) / OH;

        float q0 = 0.f, q1 = 0.f, q2 = 0.f, q3 = 0.f;
        #pragma unroll 4
        for (int xx = off + sx; xx < off + ex; ++xx) {
            q0 += cs[0][oy][xx];
            q1 += cs[1][oy][xx];
            q2 += cs[2][oy][xx];
            q3 += cs[3][oy][xx];
        }

        const float inv = 1.0f / (float)((ey - sy) * (ex - sx));
        obase[t]               = q0 * inv;
        obase[t +     OH * OW] = q1 * inv;
        obase[t + 2 * OH * OW] = q2 * inv;
        obase[t + 3 * OH * OW] = q3 * inv;
    }
}

extern "C" void kernel_launch(void* const* d_in, const int* in_sizes, int n_in,
                              void* d_out, int out_size)
{
    const float* x    = (const float*)d_in[0];
    const int*   rois = (const int*)d_in[1];
    float*       out  = (float*)d_out;

    roi_pool_ren_kernel<<<NBLOCK, THREADS>>>(x, rois, out);
}